// round 7
// baseline (speedup 1.0000x reference)
#include <cuda_runtime.h>
#include <cuda_bf16.h>

#define T_LEN 128
#define BATCH 512
#define DIN   768

typedef unsigned long long ull;
typedef unsigned int uint32;

// ---------------- scratch (static device arrays; no allocation) ----------------
static __device__ float g_xproj[T_LEN * BATCH * 64];   // bi-LSTM gate pre-activations (x part + bias)
static __device__ float g_h[T_LEN * BATCH * 16];       // concat(h_f, h_b)
static __device__ float g_z[T_LEN * BATCH * 16];       // ptr-LSTM hidden states
static __device__ __nv_bfloat16 g_Wbh[64 * DIN];       // bf16-hi of combined weight, [n][k]
static __device__ __nv_bfloat16 g_Wbl[64 * DIN];       // bf16-lo residual, [n][k]
static __device__ float g_bc[64];                      // combined bias

// ---------------- helpers ----------------
__device__ __forceinline__ float ex2f(float x) {
    float r; asm("ex2.approx.ftz.f32 %0, %1;" : "=f"(r) : "f"(x)); return r;
}
__device__ __forceinline__ float sigf(float x) {
    return __fdividef(1.f, 1.f + __expf(-x));
}
__device__ __forceinline__ float tanhf_fast(float x) {
    float e = __expf(2.f * x);
    return 1.f - __fdividef(2.f, e + 1.f);
}
// pack two f32 -> bf16x2 (first arg -> low half)
__device__ __forceinline__ uint32 packbf(float lo, float hi) {
    uint32 r; asm("cvt.rn.bf16x2.f32 %0, %1, %2;" : "=r"(r) : "f"(hi), "f"(lo)); return r;
}
__device__ __forceinline__ float bflo(uint32 p) { return __uint_as_float(p << 16); }
__device__ __forceinline__ float bfhi(uint32 p) { return __uint_as_float(p & 0xffff0000u); }

// bf16 mma m16n8k16, row.col, f32 accumulate
__device__ __forceinline__ void mma_bf16(float* d, const uint32* a, const uint32* b) {
    asm volatile(
        "mma.sync.aligned.m16n8k16.row.col.f32.bf16.bf16.f32 "
        "{%0,%1,%2,%3}, {%4,%5,%6,%7}, {%8,%9}, {%0,%1,%2,%3};"
        : "+f"(d[0]), "+f"(d[1]), "+f"(d[2]), "+f"(d[3])
        : "r"(a[0]), "r"(a[1]), "r"(a[2]), "r"(a[3]), "r"(b[0]), "r"(b[1]));
}

// ---------------- K0: build combined weight, bf16 hi/lo, transposed [n][k] ----------------
__global__ __launch_bounds__(256) void k_prep(
    const float* __restrict__ Wih_f, const float* __restrict__ Wih_b,
    const float* __restrict__ bih_f, const float* __restrict__ bhh_f,
    const float* __restrict__ bih_b, const float* __restrict__ bhh_b)
{
    int n = blockIdx.y;
    int k = blockIdx.x * 256 + threadIdx.x;
    float w = (n < 32) ? Wih_f[n * DIN + k] : Wih_b[(n - 32) * DIN + k];
    __nv_bfloat16 hi = __float2bfloat16_rn(w);
    float res = w - __bfloat162float(hi);
    g_Wbh[n * DIN + k] = hi;
    g_Wbl[n * DIN + k] = __float2bfloat16_rn(res);
    if (blockIdx.x == 0 && blockIdx.y == 0 && threadIdx.x < 64) {
        int i = threadIdx.x;
        g_bc[i] = (i < 32) ? (bih_f[i] + bhh_f[i]) : (bih_b[i - 32] + bhh_b[i - 32]);
    }
}

// ---------------- K1: xproj = X (65536x768) @ Wc (768x64) + bc  (bf16 tensor cores) ----------------
#define XPITCH 40
__global__ __launch_bounds__(256, 2) void k_gemm_xproj(const float* __restrict__ X)
{
    __shared__ __nv_bfloat16 Xh[128 * XPITCH];
    __shared__ __nv_bfloat16 Xl[128 * XPITCH];
    __shared__ __nv_bfloat16 Wh[64 * XPITCH];
    __shared__ __nv_bfloat16 Wl[64 * XPITCH];

    const int tid = threadIdx.x;
    const int rowBase = blockIdx.x * 128;
    const int w = tid >> 5;        // warp 0..7 -> rows w*16..w*16+15
    const int lane = tid & 31;
    const int g = lane >> 2;       // groupID 0..7
    const int t4 = lane & 3;       // threadID in group

    float acc[8][4];
#pragma unroll
    for (int nt = 0; nt < 8; nt++)
#pragma unroll
        for (int q = 0; q < 4; q++) acc[nt][q] = 0.f;

    float4 vx[4];
    ull vwh[2], vwl[2];

    // prefetch chunk 0
#pragma unroll
    for (int i = 0; i < 4; i++) {
        int idx = i * 256 + tid;
        int r = idx >> 3, k4 = (idx & 7) * 4;
        vx[i] = *(const float4*)(X + (size_t)(rowBase + r) * DIN + k4);
    }
#pragma unroll
    for (int i = 0; i < 2; i++) {
        int idx = i * 256 + tid;
        int n = idx >> 3, k8 = (idx & 7) * 4;
        vwh[i] = *(const ull*)(g_Wbh + n * DIN + k8);
        vwl[i] = *(const ull*)(g_Wbl + n * DIN + k8);
    }

    for (int c = 0; c < 24; c++) {
        // stage current chunk into smem (bf16 hi/lo)
#pragma unroll
        for (int i = 0; i < 4; i++) {
            int idx = i * 256 + tid;
            int r = idx >> 3, k4 = (idx & 7) * 4;
            float4 v = vx[i];
            __nv_bfloat16 hx = __float2bfloat16_rn(v.x);
            __nv_bfloat16 hy = __float2bfloat16_rn(v.y);
            __nv_bfloat16 hz = __float2bfloat16_rn(v.z);
            __nv_bfloat16 hw = __float2bfloat16_rn(v.w);
            *(__nv_bfloat162*)&Xh[r * XPITCH + k4 + 0] = __nv_bfloat162(hx, hy);
            *(__nv_bfloat162*)&Xh[r * XPITCH + k4 + 2] = __nv_bfloat162(hz, hw);
            *(__nv_bfloat162*)&Xl[r * XPITCH + k4 + 0] = __nv_bfloat162(
                __float2bfloat16_rn(v.x - __bfloat162float(hx)),
                __float2bfloat16_rn(v.y - __bfloat162float(hy)));
            *(__nv_bfloat162*)&Xl[r * XPITCH + k4 + 2] = __nv_bfloat162(
                __float2bfloat16_rn(v.z - __bfloat162float(hz)),
                __float2bfloat16_rn(v.w - __bfloat162float(hw)));
        }
#pragma unroll
        for (int i = 0; i < 2; i++) {
            int idx = i * 256 + tid;
            int n = idx >> 3, k8 = (idx & 7) * 4;
            *(ull*)&Wh[n * XPITCH + k8] = vwh[i];
            *(ull*)&Wl[n * XPITCH + k8] = vwl[i];
        }
        __syncthreads();

        // prefetch next chunk
        if (c < 23) {
            int k0 = (c + 1) * 32;
#pragma unroll
            for (int i = 0; i < 4; i++) {
                int idx = i * 256 + tid;
                int r = idx >> 3, k4 = (idx & 7) * 4;
                vx[i] = *(const float4*)(X + (size_t)(rowBase + r) * DIN + k0 + k4);
            }
#pragma unroll
            for (int i = 0; i < 2; i++) {
                int idx = i * 256 + tid;
                int n = idx >> 3, k8 = (idx & 7) * 4;
                vwh[i] = *(const ull*)(g_Wbh + n * DIN + k0 + k8);
                vwl[i] = *(const ull*)(g_Wbl + n * DIN + k0 + k8);
            }
        }

        // compute: 2 k16 steps
#pragma unroll
        for (int ks = 0; ks < 2; ks++) {
            const int kb = ks * 16 + 2 * t4;
            const int r0 = (w * 16 + g) * XPITCH;
            uint32 ah[4], al[4];
            ah[0] = *(const uint32*)&Xh[r0 + kb];
            ah[1] = *(const uint32*)&Xh[r0 + 8 * XPITCH + kb];
            ah[2] = *(const uint32*)&Xh[r0 + kb + 8];
            ah[3] = *(const uint32*)&Xh[r0 + 8 * XPITCH + kb + 8];
            al[0] = *(const uint32*)&Xl[r0 + kb];
            al[1] = *(const uint32*)&Xl[r0 + 8 * XPITCH + kb];
            al[2] = *(const uint32*)&Xl[r0 + kb + 8];
            al[3] = *(const uint32*)&Xl[r0 + 8 * XPITCH + kb + 8];
#pragma unroll
            for (int nt = 0; nt < 8; nt++) {
                int n = nt * 8 + g;
                uint32 bh[2], bl[2];
                bh[0] = *(const uint32*)&Wh[n * XPITCH + kb];
                bh[1] = *(const uint32*)&Wh[n * XPITCH + kb + 8];
                bl[0] = *(const uint32*)&Wl[n * XPITCH + kb];
                bl[1] = *(const uint32*)&Wl[n * XPITCH + kb + 8];
                mma_bf16(acc[nt], ah, bh);
                mma_bf16(acc[nt], ah, bl);
                mma_bf16(acc[nt], al, bh);
            }
        }
        __syncthreads();
    }

    // write out with bias
    const int r0 = rowBase + w * 16 + g;
#pragma unroll
    for (int nt = 0; nt < 8; nt++) {
        int cbase = nt * 8 + 2 * t4;
        float b0 = g_bc[cbase], b1 = g_bc[cbase + 1];
        *(float2*)(g_xproj + (size_t)r0 * 64 + cbase) = make_float2(acc[nt][0] + b0, acc[nt][1] + b1);
        *(float2*)(g_xproj + (size_t)(r0 + 8) * 64 + cbase) = make_float2(acc[nt][2] + b0, acc[nt][3] + b1);
    }
}

// ---------------- K2: bi-LSTM scan, 64-thread blocks x 128 blocks ----------------
__global__ __launch_bounds__(64) void k_bilstm(
    const float* __restrict__ Whh_f, const float* __restrict__ Whh_b)
{
    int gt = blockIdx.x * 64 + threadIdx.x;  // 0..8191
    int j   = gt & 7;
    int grp = gt >> 3;        // 0..1023
    int dir = grp >> 9;       // 0 fwd, 1 bwd
    int b   = grp & 511;
    const float* Whh = dir ? Whh_b : Whh_f;

    float w[4][8];
#pragma unroll
    for (int gi = 0; gi < 4; gi++)
#pragma unroll
        for (int k = 0; k < 8; k++) w[gi][k] = Whh[(gi * 8 + j) * 8 + k];

    float h = 0.f, c = 0.f;
    const int lanebase = (threadIdx.x & 31) & ~7;

    int t0 = dir ? (T_LEN - 1) : 0;
    int t1 = dir ? (T_LEN - 2) : 1;
    const float* xp0 = g_xproj + ((size_t)t0 * BATCH + b) * 64 + dir * 32;
    const float* xp1 = g_xproj + ((size_t)t1 * BATCH + b) * 64 + dir * 32;
    float n0 = xp0[j], n1 = xp0[8 + j], n2 = xp0[16 + j], n3 = xp0[24 + j];
    float m0 = xp1[j], m1 = xp1[8 + j], m2 = xp1[16 + j], m3 = xp1[24 + j];

    for (int s = 0; s < T_LEN; s++) {
        int t = dir ? (T_LEN - 1 - s) : s;
        float p0 = n0, p1 = n1, p2 = n2, p3 = n3;
        n0 = m0; n1 = m1; n2 = m2; n3 = m3;
        if (s < T_LEN - 2) {
            int tn = dir ? (T_LEN - 3 - s) : (s + 2);
            const float* xn = g_xproj + ((size_t)tn * BATCH + b) * 64 + dir * 32;
            m0 = xn[j]; m1 = xn[8 + j]; m2 = xn[16 + j]; m3 = xn[24 + j];
        }
#pragma unroll
        for (int k = 0; k < 8; k++) {
            float hk = __shfl_sync(0xffffffffu, h, lanebase + k);
            p0 += w[0][k] * hk;
            p1 += w[1][k] * hk;
            p2 += w[2][k] * hk;
            p3 += w[3][k] * hk;
        }
        float ig = sigf(p0), fg = sigf(p1), gg = tanhf_fast(p2), og = sigf(p3);
        c = fg * c + ig * gg;
        h = og * tanhf_fast(c);
        g_h[((size_t)t * BATCH + b) * 16 + dir * 8 + j] = h;
    }
}

// ---------------- K3: ptr-LSTM scan with fused input projection ----------------
// input x_t = h_t[b] (16-dim). Each thread j owns gate rows {j,16+j,32+j,48+j},
// weights [Wih | Whh] = 4x32 in registers. 32-dim [x;h] gathered via shuffles.
__global__ __launch_bounds__(64) void k_ptrlstm(
    const float* __restrict__ Wih_p, const float* __restrict__ Whh_p,
    const float* __restrict__ bih_p, const float* __restrict__ bhh_p)
{
    int gt = blockIdx.x * 64 + threadIdx.x;  // 0..8191
    int j = gt & 15;
    int b = gt >> 4;  // 0..511

    float w[4][32];
    float bias[4];
#pragma unroll
    for (int gi = 0; gi < 4; gi++) {
        int row = gi * 16 + j;
#pragma unroll
        for (int k = 0; k < 16; k++) w[gi][k] = Wih_p[row * 16 + k];
#pragma unroll
        for (int k = 0; k < 16; k++) w[gi][16 + k] = Whh_p[row * 16 + k];
        bias[gi] = bih_p[row] + bhh_p[row];
    }

    float h = 0.f, c = 0.f;
    const int lanebase = (threadIdx.x & 31) & ~15;

    float x0 = g_h[(size_t)b * 16 + j];
    float x1 = g_h[((size_t)BATCH + b) * 16 + j];

    for (int t = 0; t < T_LEN; t++) {
        float xv = x0;
        x0 = x1;
        if (t < T_LEN - 2) x1 = g_h[((size_t)(t + 2) * BATCH + b) * 16 + j];
        float p0 = bias[0], p1 = bias[1], p2 = bias[2], p3 = bias[3];
#pragma unroll
        for (int k = 0; k < 16; k++) {
            float xk = __shfl_sync(0xffffffffu, xv, lanebase + k);
            p0 += w[0][k] * xk;
            p1 += w[1][k] * xk;
            p2 += w[2][k] * xk;
            p3 += w[3][k] * xk;
        }
#pragma unroll
        for (int k = 0; k < 16; k++) {
            float hk = __shfl_sync(0xffffffffu, h, lanebase + k);
            p0 += w[0][16 + k] * hk;
            p1 += w[1][16 + k] * hk;
            p2 += w[2][16 + k] * hk;
            p3 += w[3][16 + k] * hk;
        }
        float ig = sigf(p0), fg = sigf(p1), gg = tanhf_fast(p2), og = sigf(p3);
        c = fg * c + ig * gg;
        h = og * tanhf_fast(c);
        g_z[((size_t)t * BATCH + b) * 16 + j] = h;
    }
}

// ---------------- K4: tensor-core attention + output head, one CTA per t ----------------
// S[b,c] = h_b . z_c via bf16 hi/lo 3-term mma (z pre-scaled by log2e).
// E = 2^S; colsum over b per c; ctx[b] = sum_c E[b,c]*inv_c*h[c] via second mma
// whose A-fragments are EXACTLY the exp'd D-fragments of the first.
#define HP 20
#define HTP 516
#define OFF_HHI   0
#define OFF_HLO   20480
#define OFF_ZHI   40960
#define OFF_ZLO   61440
#define OFF_HT    81920
#define OFF_CP    114944
#define OFF_INV   117248
#define OFF_CTX   117376
#define OFF_WH    152192
#define OFF_WE    153216
#define OFF_WV    154240
#define ATT_SMEM  154304

__global__ __launch_bounds__(512, 1) void k_attn(
    const float* __restrict__ W_h, const float* __restrict__ W_e,
    const float* __restrict__ W_v, float* __restrict__ out)
{
    extern __shared__ char smc[];
    __nv_bfloat16* hhi = (__nv_bfloat16*)(smc + OFF_HHI);
    __nv_bfloat16* hlo = (__nv_bfloat16*)(smc + OFF_HLO);
    __nv_bfloat16* zhi = (__nv_bfloat16*)(smc + OFF_ZHI);
    __nv_bfloat16* zlo = (__nv_bfloat16*)(smc + OFF_ZLO);
    float* hT   = (float*)(smc + OFF_HT);
    float* cp   = (float*)(smc + OFF_CP);
    float* invs = (float*)(smc + OFF_INV);
    float* ctx  = (float*)(smc + OFF_CTX);
    float* sWh  = (float*)(smc + OFF_WH);
    float* sWe  = (float*)(smc + OFF_WE);
    float* sWv  = (float*)(smc + OFF_WV);

    const int t = blockIdx.x, tid = threadIdx.x;
    const int w = tid >> 5, lane = tid & 31;
    const int qr = lane >> 2, qc = lane & 3;
    const float LOG2E = 1.4426950408889634f;

    const float4* hg = (const float4*)(g_h + (size_t)t * 8192);
    const float4* zg = (const float4*)(g_z + (size_t)t * 8192);
#pragma unroll
    for (int it = 0; it < 4; it++) {
        int i = it * 512 + tid;
        int r = i >> 2, d4 = (i & 3) * 4;
        float4 v = hg[i];
        uint32 h01 = packbf(v.x, v.y), h23 = packbf(v.z, v.w);
        *(uint32*)&hhi[r * HP + d4]     = h01;
        *(uint32*)&hhi[r * HP + d4 + 2] = h23;
        *(uint32*)&hlo[r * HP + d4]     = packbf(v.x - bflo(h01), v.y - bfhi(h01));
        *(uint32*)&hlo[r * HP + d4 + 2] = packbf(v.z - bflo(h23), v.w - bfhi(h23));
        hT[(d4 + 0) * HTP + r] = v.x;
        hT[(d4 + 1) * HTP + r] = v.y;
        hT[(d4 + 2) * HTP + r] = v.z;
        hT[(d4 + 3) * HTP + r] = v.w;
        float4 u = zg[i];
        u.x *= LOG2E; u.y *= LOG2E; u.z *= LOG2E; u.w *= LOG2E;
        uint32 z01 = packbf(u.x, u.y), z23 = packbf(u.z, u.w);
        *(uint32*)&zhi[r * HP + d4]     = z01;
        *(uint32*)&zhi[r * HP + d4 + 2] = z23;
        *(uint32*)&zlo[r * HP + d4]     = packbf(u.x - bflo(z01), u.y - bfhi(z01));
        *(uint32*)&zlo[r * HP + d4 + 2] = packbf(u.z - bflo(z23), u.w - bfhi(z23));
    }
    if (tid < 256) { sWh[tid] = W_h[tid]; sWe[tid] = W_e[tid]; }
    if (tid < 16)  sWv[tid] = W_v[tid];
    __syncthreads();

    uint32 Ahh[2][4], Ahl[2][4];
#pragma unroll
    for (int mt = 0; mt < 2; mt++) {
        int row = 32 * w + 16 * mt + qr;
        int base = row * HP + 2 * qc;
        Ahh[mt][0] = *(const uint32*)&hhi[base];
        Ahh[mt][1] = *(const uint32*)&hhi[base + 8 * HP];
        Ahh[mt][2] = *(const uint32*)&hhi[base + 8];
        Ahh[mt][3] = *(const uint32*)&hhi[base + 8 * HP + 8];
        Ahl[mt][0] = *(const uint32*)&hlo[base];
        Ahl[mt][1] = *(const uint32*)&hlo[base + 8 * HP];
        Ahl[mt][2] = *(const uint32*)&hlo[base + 8];
        Ahl[mt][3] = *(const uint32*)&hlo[base + 8 * HP + 8];
    }

    float ctxacc[2][2][4];
#pragma unroll
    for (int mt = 0; mt < 2; mt++)
#pragma unroll
        for (int nt = 0; nt < 2; nt++)
#pragma unroll
            for (int q = 0; q < 4; q++) ctxacc[mt][nt][q] = 0.f;

    for (int tile = 0; tile < 16; tile++) {
        const int c0 = tile * 32;
        uint32 Aeh[2][2][4], Ael[2][2][4];

#pragma unroll
        for (int nt = 0; nt < 4; nt++) {
            int crow = c0 + 8 * nt + qr;
            int zb = crow * HP + 2 * qc;
            uint32 bzh[2], bzl[2];
            bzh[0] = *(const uint32*)&zhi[zb];
            bzh[1] = *(const uint32*)&zhi[zb + 8];
            bzl[0] = *(const uint32*)&zlo[zb];
            bzl[1] = *(const uint32*)&zlo[zb + 8];
            float P0 = 0.f, P1 = 0.f;
            const int ks = nt >> 1, hf = nt & 1;
#pragma unroll
            for (int mt = 0; mt < 2; mt++) {
                float S[4] = {0.f, 0.f, 0.f, 0.f};
                mma_bf16(S, Ahh[mt], bzh);
                mma_bf16(S, Ahh[mt], bzl);
                mma_bf16(S, Ahl[mt], bzh);
                float e0 = ex2f(S[0]), e1 = ex2f(S[1]), e2 = ex2f(S[2]), e3 = ex2f(S[3]);
                P0 += e0 + e2; P1 += e1 + e3;
                uint32 p01 = packbf(e0, e1), p23 = packbf(e2, e3);
                Aeh[mt][ks][2 * hf]     = p01;
                Aeh[mt][ks][2 * hf + 1] = p23;
                Ael[mt][ks][2 * hf]     = packbf(e0 - bflo(p01), e1 - bfhi(p01));
                Ael[mt][ks][2 * hf + 1] = packbf(e2 - bflo(p23), e3 - bfhi(p23));
            }
            P0 += __shfl_xor_sync(0xffffffffu, P0, 4);
            P0 += __shfl_xor_sync(0xffffffffu, P0, 8);
            P0 += __shfl_xor_sync(0xffffffffu, P0, 16);
            P1 += __shfl_xor_sync(0xffffffffu, P1, 4);
            P1 += __shfl_xor_sync(0xffffffffu, P1, 8);
            P1 += __shfl_xor_sync(0xffffffffu, P1, 16);
            if (qr == 0) {
                cp[w * 36 + 8 * nt + 2 * qc]     = P0;
                cp[w * 36 + 8 * nt + 2 * qc + 1] = P1;
            }
        }
        __syncthreads();
        if (tid < 32) {
            float s = 0.f;
#pragma unroll
            for (int ww = 0; ww < 16; ww++) s += cp[ww * 36 + tid];
            invs[tid] = __fdividef(1.f, s);
        }
        __syncthreads();

#pragma unroll
        for (int ks = 0; ks < 2; ks++) {
#pragma unroll
            for (int nt2 = 0; nt2 < 2; nt2++) {
                int d = 8 * nt2 + qr;
                int cc = 16 * ks + 2 * qc;
                float i0 = invs[cc], i1 = invs[cc + 1], i8 = invs[cc + 8], i9 = invs[cc + 9];
                const float* hr = hT + d * HTP + c0 + cc;
                float v0 = hr[0] * i0, v1 = hr[1] * i1, v8 = hr[8] * i8, v9 = hr[9] * i9;
                uint32 bh[2], bl[2];
                bh[0] = packbf(v0, v1);
                bh[1] = packbf(v8, v9);
                bl[0] = packbf(v0 - bflo(bh[0]), v1 - bfhi(bh[0]));
                bl[1] = packbf(v8 - bflo(bh[1]), v9 - bfhi(bh[1]));
#pragma unroll
                for (int mt = 0; mt < 2; mt++) {
                    mma_bf16(ctxacc[mt][nt2], Aeh[mt][ks], bh);
                    mma_bf16(ctxacc[mt][nt2], Ael[mt][ks], bh);
                    mma_bf16(ctxacc[mt][nt2], Aeh[mt][ks], bl);
                }
            }
        }
    }

#pragma unroll
    for (int mt = 0; mt < 2; mt++)
#pragma unroll
        for (int nt2 = 0; nt2 < 2; nt2++) {
            int row = 32 * w + 16 * mt + qr;
            int col = 8 * nt2 + 2 * qc;
            ctx[row * 17 + col]           = ctxacc[mt][nt2][0];
            ctx[row * 17 + col + 1]       = ctxacc[mt][nt2][1];
            ctx[(row + 8) * 17 + col]     = ctxacc[mt][nt2][2];
            ctx[(row + 8) * 17 + col + 1] = ctxacc[mt][nt2][3];
        }
    __syncthreads();

    {
        int b = tid;
        float hb[16], cx[16];
        const float4* hp4 = (const float4*)(g_h + (size_t)t * 8192 + b * 16);
#pragma unroll
        for (int q = 0; q < 4; q++) {
            float4 v = hp4[q];
            hb[4 * q + 0] = v.x; hb[4 * q + 1] = v.y; hb[4 * q + 2] = v.z; hb[4 * q + 3] = v.w;
        }
#pragma unroll
        for (int k = 0; k < 16; k++) cx[k] = ctx[b * 17 + k];
        float pv = 0.f;
#pragma unroll
        for (int r = 0; r < 16; r++) {
            float a = 0.f;
#pragma unroll
            for (int k = 0; k < 16; k++)
                a += sWh[r * 16 + k] * hb[k] + sWe[r * 16 + k] * cx[k];
            pv += sWv[r] * tanhf_fast(a);
        }
        out[(size_t)t * BATCH + b] = sigf(pv);
    }
}

// ---------------- launch ----------------
extern "C" void kernel_launch(void* const* d_in, const int* in_sizes, int n_in,
                              void* d_out, int out_size)
{
    const float* X     = (const float*)d_in[0];
    const float* Wih_f = (const float*)d_in[1];
    const float* Whh_f = (const float*)d_in[2];
    const float* bih_f = (const float*)d_in[3];
    const float* bhh_f = (const float*)d_in[4];
    const float* Wih_b = (const float*)d_in[5];
    const float* Whh_b = (const float*)d_in[6];
    const float* bih_b = (const float*)d_in[7];
    const float* bhh_b = (const float*)d_in[8];
    const float* Wih_p = (const float*)d_in[9];
    const float* Whh_p = (const float*)d_in[10];
    const float* bih_p = (const float*)d_in[11];
    const float* bhh_p = (const float*)d_in[12];
    const float* W_h   = (const float*)d_in[13];
    const float* W_e   = (const float*)d_in[14];
    const float* W_v   = (const float*)d_in[15];
    float* out = (float*)d_out;

    cudaFuncSetAttribute((const void*)k_attn, cudaFuncAttributeMaxDynamicSharedMemorySize, 160 * 1024);

    k_prep<<<dim3(3, 64), 256>>>(Wih_f, Wih_b, bih_f, bhh_f, bih_b, bhh_b);
    k_gemm_xproj<<<(T_LEN * BATCH) / 128, 256>>>(X);
    k_bilstm<<<128, 64>>>(Whh_f, Whh_b);
    k_ptrlstm<<<128, 64>>>(Wih_p, Whh_p, bih_p, bhh_p);
    k_attn<<<T_LEN, 512, ATT_SMEM>>>(W_h, W_e, W_v, out);
}

// round 8
// speedup vs baseline: 1.1462x; 1.1462x over previous
#include <cuda_runtime.h>
#include <cuda_bf16.h>

#define T_LEN 128
#define BATCH 512
#define DIN   768

typedef unsigned long long ull;
typedef unsigned int uint32;

// ---------------- scratch (static device arrays; no allocation) ----------------
static __device__ float g_xproj[T_LEN * BATCH * 64];   // bi-LSTM gate pre-activations (x part + bias)
static __device__ float g_h[T_LEN * BATCH * 16];       // concat(h_f, h_b)
static __device__ float g_z[T_LEN * BATCH * 16];       // ptr-LSTM hidden states
static __device__ __nv_bfloat16 g_Wbh[64 * DIN];       // bf16-hi of combined weight, [n][k]
static __device__ __nv_bfloat16 g_Wbl[64 * DIN];       // bf16-lo residual, [n][k]
static __device__ float g_bc[64];                      // combined bias

// ---------------- helpers ----------------
__device__ __forceinline__ float ex2f(float x) {
    float r; asm("ex2.approx.ftz.f32 %0, %1;" : "=f"(r) : "f"(x)); return r;
}
__device__ __forceinline__ float sigf(float x) {
    return __fdividef(1.f, 1.f + __expf(-x));
}
__device__ __forceinline__ float tanhf_fast(float x) {
    float e = __expf(2.f * x);
    return 1.f - __fdividef(2.f, e + 1.f);
}
// f32x2 packed math
__device__ __forceinline__ ull fma2(ull a, ull b, ull c) {
    ull d; asm("fma.rn.f32x2 %0, %1, %2, %3;" : "=l"(d) : "l"(a), "l"(b), "l"(c)); return d;
}
__device__ __forceinline__ ull pack2(float x, float y) {
    ull d; asm("mov.b64 %0, {%1, %2};" : "=l"(d) : "f"(x), "f"(y)); return d;
}
__device__ __forceinline__ float2 unpack2(ull v) {
    float2 r; asm("mov.b64 {%0, %1}, %2;" : "=f"(r.x), "=f"(r.y) : "l"(v)); return r;
}
// pack two f32 -> bf16x2 (first arg -> low half)
__device__ __forceinline__ uint32 packbf(float lo, float hi) {
    uint32 r; asm("cvt.rn.bf16x2.f32 %0, %1, %2;" : "=r"(r) : "f"(hi), "f"(lo)); return r;
}
__device__ __forceinline__ float bflo(uint32 p) { return __uint_as_float(p << 16); }
__device__ __forceinline__ float bfhi(uint32 p) { return __uint_as_float(p & 0xffff0000u); }

// bf16 mma m16n8k16, row.col, f32 accumulate
__device__ __forceinline__ void mma_bf16(float* d, const uint32* a, const uint32* b) {
    asm volatile(
        "mma.sync.aligned.m16n8k16.row.col.f32.bf16.bf16.f32 "
        "{%0,%1,%2,%3}, {%4,%5,%6,%7}, {%8,%9}, {%0,%1,%2,%3};"
        : "+f"(d[0]), "+f"(d[1]), "+f"(d[2]), "+f"(d[3])
        : "r"(a[0]), "r"(a[1]), "r"(a[2]), "r"(a[3]), "r"(b[0]), "r"(b[1]));
}

// ---------------- K0: build combined weight, bf16 hi/lo, transposed [n][k] ----------------
__global__ __launch_bounds__(256) void k_prep(
    const float* __restrict__ Wih_f, const float* __restrict__ Wih_b,
    const float* __restrict__ bih_f, const float* __restrict__ bhh_f,
    const float* __restrict__ bih_b, const float* __restrict__ bhh_b)
{
    int n = blockIdx.y;
    int k = blockIdx.x * 256 + threadIdx.x;
    float w = (n < 32) ? Wih_f[n * DIN + k] : Wih_b[(n - 32) * DIN + k];
    __nv_bfloat16 hi = __float2bfloat16_rn(w);
    float res = w - __bfloat162float(hi);
    g_Wbh[n * DIN + k] = hi;
    g_Wbl[n * DIN + k] = __float2bfloat16_rn(res);
    if (blockIdx.x == 0 && blockIdx.y == 0 && threadIdx.x < 64) {
        int i = threadIdx.x;
        g_bc[i] = (i < 32) ? (bih_f[i] + bhh_f[i]) : (bih_b[i - 32] + bhh_b[i - 32]);
    }
}

// ---------------- K1: xproj = X (65536x768) @ Wc (768x64) + bc  (bf16 tensor cores) ----------------
#define XPITCH 40
__global__ __launch_bounds__(256, 2) void k_gemm_xproj(const float* __restrict__ X)
{
    __shared__ __nv_bfloat16 Xh[128 * XPITCH];
    __shared__ __nv_bfloat16 Xl[128 * XPITCH];
    __shared__ __nv_bfloat16 Wh[64 * XPITCH];
    __shared__ __nv_bfloat16 Wl[64 * XPITCH];

    const int tid = threadIdx.x;
    const int rowBase = blockIdx.x * 128;
    const int w = tid >> 5;
    const int lane = tid & 31;
    const int g = lane >> 2;
    const int t4 = lane & 3;

    float acc[8][4];
#pragma unroll
    for (int nt = 0; nt < 8; nt++)
#pragma unroll
        for (int q = 0; q < 4; q++) acc[nt][q] = 0.f;

    float4 vx[4];
    ull vwh[2], vwl[2];

#pragma unroll
    for (int i = 0; i < 4; i++) {
        int idx = i * 256 + tid;
        int r = idx >> 3, k4 = (idx & 7) * 4;
        vx[i] = *(const float4*)(X + (size_t)(rowBase + r) * DIN + k4);
    }
#pragma unroll
    for (int i = 0; i < 2; i++) {
        int idx = i * 256 + tid;
        int n = idx >> 3, k8 = (idx & 7) * 4;
        vwh[i] = *(const ull*)(g_Wbh + n * DIN + k8);
        vwl[i] = *(const ull*)(g_Wbl + n * DIN + k8);
    }

    for (int c = 0; c < 24; c++) {
#pragma unroll
        for (int i = 0; i < 4; i++) {
            int idx = i * 256 + tid;
            int r = idx >> 3, k4 = (idx & 7) * 4;
            float4 v = vx[i];
            __nv_bfloat16 hx = __float2bfloat16_rn(v.x);
            __nv_bfloat16 hy = __float2bfloat16_rn(v.y);
            __nv_bfloat16 hz = __float2bfloat16_rn(v.z);
            __nv_bfloat16 hw = __float2bfloat16_rn(v.w);
            *(__nv_bfloat162*)&Xh[r * XPITCH + k4 + 0] = __nv_bfloat162(hx, hy);
            *(__nv_bfloat162*)&Xh[r * XPITCH + k4 + 2] = __nv_bfloat162(hz, hw);
            *(__nv_bfloat162*)&Xl[r * XPITCH + k4 + 0] = __nv_bfloat162(
                __float2bfloat16_rn(v.x - __bfloat162float(hx)),
                __float2bfloat16_rn(v.y - __bfloat162float(hy)));
            *(__nv_bfloat162*)&Xl[r * XPITCH + k4 + 2] = __nv_bfloat162(
                __float2bfloat16_rn(v.z - __bfloat162float(hz)),
                __float2bfloat16_rn(v.w - __bfloat162float(hw)));
        }
#pragma unroll
        for (int i = 0; i < 2; i++) {
            int idx = i * 256 + tid;
            int n = idx >> 3, k8 = (idx & 7) * 4;
            *(ull*)&Wh[n * XPITCH + k8] = vwh[i];
            *(ull*)&Wl[n * XPITCH + k8] = vwl[i];
        }
        __syncthreads();

        if (c < 23) {
            int k0 = (c + 1) * 32;
#pragma unroll
            for (int i = 0; i < 4; i++) {
                int idx = i * 256 + tid;
                int r = idx >> 3, k4 = (idx & 7) * 4;
                vx[i] = *(const float4*)(X + (size_t)(rowBase + r) * DIN + k0 + k4);
            }
#pragma unroll
            for (int i = 0; i < 2; i++) {
                int idx = i * 256 + tid;
                int n = idx >> 3, k8 = (idx & 7) * 4;
                vwh[i] = *(const ull*)(g_Wbh + n * DIN + k0 + k8);
                vwl[i] = *(const ull*)(g_Wbl + n * DIN + k0 + k8);
            }
        }

#pragma unroll
        for (int ks = 0; ks < 2; ks++) {
            const int kb = ks * 16 + 2 * t4;
            const int r0 = (w * 16 + g) * XPITCH;
            uint32 ah[4], al[4];
            ah[0] = *(const uint32*)&Xh[r0 + kb];
            ah[1] = *(const uint32*)&Xh[r0 + 8 * XPITCH + kb];
            ah[2] = *(const uint32*)&Xh[r0 + kb + 8];
            ah[3] = *(const uint32*)&Xh[r0 + 8 * XPITCH + kb + 8];
            al[0] = *(const uint32*)&Xl[r0 + kb];
            al[1] = *(const uint32*)&Xl[r0 + 8 * XPITCH + kb];
            al[2] = *(const uint32*)&Xl[r0 + kb + 8];
            al[3] = *(const uint32*)&Xl[r0 + 8 * XPITCH + kb + 8];
#pragma unroll
            for (int nt = 0; nt < 8; nt++) {
                int n = nt * 8 + g;
                uint32 bh[2], bl[2];
                bh[0] = *(const uint32*)&Wh[n * XPITCH + kb];
                bh[1] = *(const uint32*)&Wh[n * XPITCH + kb + 8];
                bl[0] = *(const uint32*)&Wl[n * XPITCH + kb];
                bl[1] = *(const uint32*)&Wl[n * XPITCH + kb + 8];
                mma_bf16(acc[nt], ah, bh);
                mma_bf16(acc[nt], ah, bl);
                mma_bf16(acc[nt], al, bh);
            }
        }
        __syncthreads();
    }

    const int r0 = rowBase + w * 16 + g;
#pragma unroll
    for (int nt = 0; nt < 8; nt++) {
        int cbase = nt * 8 + 2 * t4;
        float b0 = g_bc[cbase], b1 = g_bc[cbase + 1];
        *(float2*)(g_xproj + (size_t)r0 * 64 + cbase) = make_float2(acc[nt][0] + b0, acc[nt][1] + b1);
        *(float2*)(g_xproj + (size_t)(r0 + 8) * 64 + cbase) = make_float2(acc[nt][2] + b0, acc[nt][3] + b1);
    }
}

// ---------------- K2: bi-LSTM scan — smem h-broadcast + f32x2 FMA (no shuffle chains) ----------------
// 64 threads = 8 groups of 8 (one per batch-item x direction slice). Double-buffered
// h broadcast through padded smem; gates accumulate with FFMA2.
__global__ __launch_bounds__(64) void k_bilstm(
    const float* __restrict__ Whh_f, const float* __restrict__ Whh_b)
{
    __shared__ float hb[2][8 * 12];   // [parity][group*12 + j], pitch 12 -> distinct banks

    const int tid = threadIdx.x;
    const int j = tid & 7;
    const int g = tid >> 3;                 // group in block 0..7
    const int grp = blockIdx.x * 8 + g;     // 0..1023
    const int dir = grp >> 9;
    const int b = grp & 511;
    const float* Whh = dir ? Whh_b : Whh_f;

    // packed recurrent weights: wp[gate][kk] = (Whh[row][2kk], Whh[row][2kk+1])
    ull wp[4][4];
#pragma unroll
    for (int gi = 0; gi < 4; gi++) {
        const float* row = Whh + (gi * 8 + j) * 8;
#pragma unroll
        for (int kk = 0; kk < 4; kk++) wp[gi][kk] = pack2(row[2 * kk], row[2 * kk + 1]);
    }

    hb[0][g * 12 + j] = 0.f;
    float c = 0.f, h = 0.f;

    // 2-deep prefetch of gate pre-activations
    int t0 = dir ? (T_LEN - 1) : 0;
    int t1 = dir ? (T_LEN - 2) : 1;
    const float* xp0 = g_xproj + ((size_t)t0 * BATCH + b) * 64 + dir * 32;
    const float* xp1 = g_xproj + ((size_t)t1 * BATCH + b) * 64 + dir * 32;
    float n0 = xp0[j], n1 = xp0[8 + j], n2 = xp0[16 + j], n3 = xp0[24 + j];
    float m0 = xp1[j], m1 = xp1[8 + j], m2 = xp1[16 + j], m3 = xp1[24 + j];
    __syncthreads();

    for (int s = 0; s < T_LEN; s++) {
        int t = dir ? (T_LEN - 1 - s) : s;
        float q0 = n0, q1 = n1, q2 = n2, q3 = n3;
        n0 = m0; n1 = m1; n2 = m2; n3 = m3;
        if (s < T_LEN - 2) {
            int tn = dir ? (T_LEN - 3 - s) : (s + 2);
            const float* xn = g_xproj + ((size_t)tn * BATCH + b) * 64 + dir * 32;
            m0 = xn[j]; m1 = xn[8 + j]; m2 = xn[16 + j]; m3 = xn[24 + j];
        }
        // load h vector of this group as 4 f32x2 pairs (broadcast reads)
        const int p = s & 1;
        ull hp[4];
        const ull* hr = (const ull*)&hb[p][g * 12];
#pragma unroll
        for (int kk = 0; kk < 4; kk++) hp[kk] = hr[kk];

        ull a0 = pack2(q0, 0.f), a1 = pack2(q1, 0.f), a2 = pack2(q2, 0.f), a3 = pack2(q3, 0.f);
#pragma unroll
        for (int kk = 0; kk < 4; kk++) {
            a0 = fma2(wp[0][kk], hp[kk], a0);
            a1 = fma2(wp[1][kk], hp[kk], a1);
            a2 = fma2(wp[2][kk], hp[kk], a2);
            a3 = fma2(wp[3][kk], hp[kk], a3);
        }
        float2 f0 = unpack2(a0), f1 = unpack2(a1), f2 = unpack2(a2), f3 = unpack2(a3);
        float ig = sigf(f0.x + f0.y), fg = sigf(f1.x + f1.y);
        float gg = tanhf_fast(f2.x + f2.y), og = sigf(f3.x + f3.y);
        c = fg * c + ig * gg;
        h = og * tanhf_fast(c);
        g_h[((size_t)t * BATCH + b) * 16 + dir * 8 + j] = h;
        hb[1 - p][g * 12 + j] = h;
        __syncwarp();
    }
}

// ---------------- K3: ptr-LSTM scan, fused input projection — smem broadcast + f32x2 ----------------
// 64 threads = 4 items x 16. x-input (g_h slab) fully staged into smem; h double-buffered.
__global__ __launch_bounds__(64) void k_ptrlstm(
    const float* __restrict__ Wih_p, const float* __restrict__ Whh_p,
    const float* __restrict__ bih_p, const float* __restrict__ bhh_p)
{
    __shared__ float xs[T_LEN * 80];   // [t*80 + item*20 + j]
    __shared__ float hb[2][4 * 20];    // [parity][item*20 + j]

    const int tid = threadIdx.x;
    const int j = tid & 15;
    const int g = tid >> 4;            // item in block 0..3
    const int bbase = blockIdx.x * 4;
    const int b = bbase + g;

    // stage x = g_h for this block's 4 items, all 128 timesteps (coalesced)
    for (int i = tid; i < 2048; i += 64) {
        int t = i >> 4, q = i & 15;
        int item = q >> 2, f4 = q & 3;
        float4 v = *(const float4*)(g_h + (size_t)t * 8192 + (bbase + item) * 16 + f4 * 4);
        *(float4*)&xs[t * 80 + item * 20 + f4 * 4] = v;
    }

    // packed weights: x pairs (kk 0..7) then h pairs (kk 8..15)
    ull wp[4][16];
    float bias[4];
#pragma unroll
    for (int gi = 0; gi < 4; gi++) {
        int row = gi * 16 + j;
        const float* wi = Wih_p + row * 16;
        const float* wh = Whh_p + row * 16;
#pragma unroll
        for (int kk = 0; kk < 8; kk++) wp[gi][kk] = pack2(wi[2 * kk], wi[2 * kk + 1]);
#pragma unroll
        for (int kk = 0; kk < 8; kk++) wp[gi][8 + kk] = pack2(wh[2 * kk], wh[2 * kk + 1]);
        bias[gi] = bih_p[row] + bhh_p[row];
    }

    hb[0][g * 20 + j] = 0.f;
    float c = 0.f;
    __syncthreads();

    for (int t = 0; t < T_LEN; t++) {
        const int p = t & 1;
        const ull* xr = (const ull*)&xs[t * 80 + g * 20];
        const ull* hr = (const ull*)&hb[p][g * 20];
        ull xh[16];
#pragma unroll
        for (int kk = 0; kk < 8; kk++) xh[kk] = xr[kk];
#pragma unroll
        for (int kk = 0; kk < 8; kk++) xh[8 + kk] = hr[kk];

        ull a0 = pack2(bias[0], 0.f), a1 = pack2(bias[1], 0.f);
        ull a2 = pack2(bias[2], 0.f), a3 = pack2(bias[3], 0.f);
#pragma unroll
        for (int kk = 0; kk < 16; kk++) {
            a0 = fma2(wp[0][kk], xh[kk], a0);
            a1 = fma2(wp[1][kk], xh[kk], a1);
            a2 = fma2(wp[2][kk], xh[kk], a2);
            a3 = fma2(wp[3][kk], xh[kk], a3);
        }
        float2 f0 = unpack2(a0), f1 = unpack2(a1), f2 = unpack2(a2), f3 = unpack2(a3);
        float ig = sigf(f0.x + f0.y), fg = sigf(f1.x + f1.y);
        float gg = tanhf_fast(f2.x + f2.y), og = sigf(f3.x + f3.y);
        c = fg * c + ig * gg;
        float h = og * tanhf_fast(c);
        g_z[((size_t)t * BATCH + b) * 16 + j] = h;
        hb[1 - p][g * 20 + j] = h;
        __syncwarp();
    }
}

// ---------------- K4: tensor-core attention + output head, one CTA per t ----------------
#define HP 20
#define HTP 516
#define OFF_HHI   0
#define OFF_HLO   20480
#define OFF_ZHI   40960
#define OFF_ZLO   61440
#define OFF_HT    81920
#define OFF_CP    114944
#define OFF_INV   117248
#define OFF_CTX   117376
#define OFF_WH    152192
#define OFF_WE    153216
#define OFF_WV    154240
#define ATT_SMEM  154304

__global__ __launch_bounds__(512, 1) void k_attn(
    const float* __restrict__ W_h, const float* __restrict__ W_e,
    const float* __restrict__ W_v, float* __restrict__ out)
{
    extern __shared__ char smc[];
    __nv_bfloat16* hhi = (__nv_bfloat16*)(smc + OFF_HHI);
    __nv_bfloat16* hlo = (__nv_bfloat16*)(smc + OFF_HLO);
    __nv_bfloat16* zhi = (__nv_bfloat16*)(smc + OFF_ZHI);
    __nv_bfloat16* zlo = (__nv_bfloat16*)(smc + OFF_ZLO);
    float* hT   = (float*)(smc + OFF_HT);
    float* cp   = (float*)(smc + OFF_CP);
    float* invs = (float*)(smc + OFF_INV);
    float* ctx  = (float*)(smc + OFF_CTX);
    float* sWh  = (float*)(smc + OFF_WH);
    float* sWe  = (float*)(smc + OFF_WE);
    float* sWv  = (float*)(smc + OFF_WV);

    const int t = blockIdx.x, tid = threadIdx.x;
    const int w = tid >> 5, lane = tid & 31;
    const int qr = lane >> 2, qc = lane & 3;
    const float LOG2E = 1.4426950408889634f;

    const float4* hg = (const float4*)(g_h + (size_t)t * 8192);
    const float4* zg = (const float4*)(g_z + (size_t)t * 8192);
#pragma unroll
    for (int it = 0; it < 4; it++) {
        int i = it * 512 + tid;
        int r = i >> 2, d4 = (i & 3) * 4;
        float4 v = hg[i];
        uint32 h01 = packbf(v.x, v.y), h23 = packbf(v.z, v.w);
        *(uint32*)&hhi[r * HP + d4]     = h01;
        *(uint32*)&hhi[r * HP + d4 + 2] = h23;
        *(uint32*)&hlo[r * HP + d4]     = packbf(v.x - bflo(h01), v.y - bfhi(h01));
        *(uint32*)&hlo[r * HP + d4 + 2] = packbf(v.z - bflo(h23), v.w - bfhi(h23));
        hT[(d4 + 0) * HTP + r] = v.x;
        hT[(d4 + 1) * HTP + r] = v.y;
        hT[(d4 + 2) * HTP + r] = v.z;
        hT[(d4 + 3) * HTP + r] = v.w;
        float4 u = zg[i];
        u.x *= LOG2E; u.y *= LOG2E; u.z *= LOG2E; u.w *= LOG2E;
        uint32 z01 = packbf(u.x, u.y), z23 = packbf(u.z, u.w);
        *(uint32*)&zhi[r * HP + d4]     = z01;
        *(uint32*)&zhi[r * HP + d4 + 2] = z23;
        *(uint32*)&zlo[r * HP + d4]     = packbf(u.x - bflo(z01), u.y - bfhi(z01));
        *(uint32*)&zlo[r * HP + d4 + 2] = packbf(u.z - bflo(z23), u.w - bfhi(z23));
    }
    if (tid < 256) { sWh[tid] = W_h[tid]; sWe[tid] = W_e[tid]; }
    if (tid < 16)  sWv[tid] = W_v[tid];
    __syncthreads();

    uint32 Ahh[2][4], Ahl[2][4];
#pragma unroll
    for (int mt = 0; mt < 2; mt++) {
        int row = 32 * w + 16 * mt + qr;
        int base = row * HP + 2 * qc;
        Ahh[mt][0] = *(const uint32*)&hhi[base];
        Ahh[mt][1] = *(const uint32*)&hhi[base + 8 * HP];
        Ahh[mt][2] = *(const uint32*)&hhi[base + 8];
        Ahh[mt][3] = *(const uint32*)&hhi[base + 8 * HP + 8];
        Ahl[mt][0] = *(const uint32*)&hlo[base];
        Ahl[mt][1] = *(const uint32*)&hlo[base + 8 * HP];
        Ahl[mt][2] = *(const uint32*)&hlo[base + 8];
        Ahl[mt][3] = *(const uint32*)&hlo[base + 8 * HP + 8];
    }

    float ctxacc[2][2][4];
#pragma unroll
    for (int mt = 0; mt < 2; mt++)
#pragma unroll
        for (int nt = 0; nt < 2; nt++)
#pragma unroll
            for (int q = 0; q < 4; q++) ctxacc[mt][nt][q] = 0.f;

    for (int tile = 0; tile < 16; tile++) {
        const int c0 = tile * 32;
        uint32 Aeh[2][2][4], Ael[2][2][4];

#pragma unroll
        for (int nt = 0; nt < 4; nt++) {
            int crow = c0 + 8 * nt + qr;
            int zb = crow * HP + 2 * qc;
            uint32 bzh[2], bzl[2];
            bzh[0] = *(const uint32*)&zhi[zb];
            bzh[1] = *(const uint32*)&zhi[zb + 8];
            bzl[0] = *(const uint32*)&zlo[zb];
            bzl[1] = *(const uint32*)&zlo[zb + 8];
            float P0 = 0.f, P1 = 0.f;
            const int ks = nt >> 1, hf = nt & 1;
#pragma unroll
            for (int mt = 0; mt < 2; mt++) {
                float S[4] = {0.f, 0.f, 0.f, 0.f};
                mma_bf16(S, Ahh[mt], bzh);
                mma_bf16(S, Ahh[mt], bzl);
                mma_bf16(S, Ahl[mt], bzh);
                float e0 = ex2f(S[0]), e1 = ex2f(S[1]), e2 = ex2f(S[2]), e3 = ex2f(S[3]);
                P0 += e0 + e2; P1 += e1 + e3;
                uint32 p01 = packbf(e0, e1), p23 = packbf(e2, e3);
                Aeh[mt][ks][2 * hf]     = p01;
                Aeh[mt][ks][2 * hf + 1] = p23;
                Ael[mt][ks][2 * hf]     = packbf(e0 - bflo(p01), e1 - bfhi(p01));
                Ael[mt][ks][2 * hf + 1] = packbf(e2 - bflo(p23), e3 - bfhi(p23));
            }
            P0 += __shfl_xor_sync(0xffffffffu, P0, 4);
            P0 += __shfl_xor_sync(0xffffffffu, P0, 8);
            P0 += __shfl_xor_sync(0xffffffffu, P0, 16);
            P1 += __shfl_xor_sync(0xffffffffu, P1, 4);
            P1 += __shfl_xor_sync(0xffffffffu, P1, 8);
            P1 += __shfl_xor_sync(0xffffffffu, P1, 16);
            if (qr == 0) {
                cp[w * 36 + 8 * nt + 2 * qc]     = P0;
                cp[w * 36 + 8 * nt + 2 * qc + 1] = P1;
            }
        }
        __syncthreads();
        if (tid < 32) {
            float s = 0.f;
#pragma unroll
            for (int ww = 0; ww < 16; ww++) s += cp[ww * 36 + tid];
            invs[tid] = __fdividef(1.f, s);
        }
        __syncthreads();

#pragma unroll
        for (int ks = 0; ks < 2; ks++) {
#pragma unroll
            for (int nt2 = 0; nt2 < 2; nt2++) {
                int d = 8 * nt2 + qr;
                int cc = 16 * ks + 2 * qc;
                float i0 = invs[cc], i1 = invs[cc + 1], i8 = invs[cc + 8], i9 = invs[cc + 9];
                const float* hr = hT + d * HTP + c0 + cc;
                float v0 = hr[0] * i0, v1 = hr[1] * i1, v8 = hr[8] * i8, v9 = hr[9] * i9;
                uint32 bh[2], bl[2];
                bh[0] = packbf(v0, v1);
                bh[1] = packbf(v8, v9);
                bl[0] = packbf(v0 - bflo(bh[0]), v1 - bfhi(bh[0]));
                bl[1] = packbf(v8 - bflo(bh[1]), v9 - bfhi(bh[1]));
#pragma unroll
                for (int mt = 0; mt < 2; mt++) {
                    mma_bf16(ctxacc[mt][nt2], Aeh[mt][ks], bh);
                    mma_bf16(ctxacc[mt][nt2], Ael[mt][ks], bh);
                    mma_bf16(ctxacc[mt][nt2], Aeh[mt][ks], bl);
                }
            }
        }
    }

#pragma unroll
    for (int mt = 0; mt < 2; mt++)
#pragma unroll
        for (int nt2 = 0; nt2 < 2; nt2++) {
            int row = 32 * w + 16 * mt + qr;
            int col = 8 * nt2 + 2 * qc;
            ctx[row * 17 + col]           = ctxacc[mt][nt2][0];
            ctx[row * 17 + col + 1]       = ctxacc[mt][nt2][1];
            ctx[(row + 8) * 17 + col]     = ctxacc[mt][nt2][2];
            ctx[(row + 8) * 17 + col + 1] = ctxacc[mt][nt2][3];
        }
    __syncthreads();

    {
        int b = tid;
        float hb2[16], cx[16];
        const float4* hp4 = (const float4*)(g_h + (size_t)t * 8192 + b * 16);
#pragma unroll
        for (int q = 0; q < 4; q++) {
            float4 v = hp4[q];
            hb2[4 * q + 0] = v.x; hb2[4 * q + 1] = v.y; hb2[4 * q + 2] = v.z; hb2[4 * q + 3] = v.w;
        }
#pragma unroll
        for (int k = 0; k < 16; k++) cx[k] = ctx[b * 17 + k];
        float pv = 0.f;
#pragma unroll
        for (int r = 0; r < 16; r++) {
            float a = 0.f;
#pragma unroll
            for (int k = 0; k < 16; k++)
                a += sWh[r * 16 + k] * hb2[k] + sWe[r * 16 + k] * cx[k];
            pv += sWv[r] * tanhf_fast(a);
        }
        out[(size_t)t * BATCH + b] = sigf(pv);
    }
}

// ---------------- launch ----------------
extern "C" void kernel_launch(void* const* d_in, const int* in_sizes, int n_in,
                              void* d_out, int out_size)
{
    const float* X     = (const float*)d_in[0];
    const float* Wih_f = (const float*)d_in[1];
    const float* Whh_f = (const float*)d_in[2];
    const float* bih_f = (const float*)d_in[3];
    const float* bhh_f = (const float*)d_in[4];
    const float* Wih_b = (const float*)d_in[5];
    const float* Whh_b = (const float*)d_in[6];
    const float* bih_b = (const float*)d_in[7];
    const float* bhh_b = (const float*)d_in[8];
    const float* Wih_p = (const float*)d_in[9];
    const float* Whh_p = (const float*)d_in[10];
    const float* bih_p = (const float*)d_in[11];
    const float* bhh_p = (const float*)d_in[12];
    const float* W_h   = (const float*)d_in[13];
    const float* W_e   = (const float*)d_in[14];
    const float* W_v   = (const float*)d_in[15];
    float* out = (float*)d_out;

    cudaFuncSetAttribute((const void*)k_attn, cudaFuncAttributeMaxDynamicSharedMemorySize, 160 * 1024);

    k_prep<<<dim3(3, 64), 256>>>(Wih_f, Wih_b, bih_f, bhh_f, bih_b, bhh_b);
    k_gemm_xproj<<<(T_LEN * BATCH) / 128, 256>>>(X);
    k_bilstm<<<128, 64>>>(Whh_f, Whh_b);
    k_ptrlstm<<<128, 64>>>(Wih_p, Whh_p, bih_p, bhh_p);
    k_attn<<<T_LEN, 512, ATT_SMEM>>>(W_h, W_e, W_v, out);
}

// round 10
// speedup vs baseline: 1.1715x; 1.0221x over previous
#include <cuda_runtime.h>
#include <cuda_bf16.h>

#define T_LEN 128
#define BATCH 512
#define DIN   768

typedef unsigned long long ull;
typedef unsigned int uint32;

// ---------------- scratch (static device arrays; no allocation) ----------------
static __device__ float g_xproj[T_LEN * BATCH * 64];   // bi-LSTM gate pre-activations (x part + bias)
static __device__ float g_h[T_LEN * BATCH * 16];       // concat(h_f, h_b)
static __device__ float g_z[T_LEN * BATCH * 16];       // ptr-LSTM hidden states
static __device__ __nv_bfloat16 g_Wbh[64 * DIN];       // bf16-hi of combined weight, [n][k]
static __device__ __nv_bfloat16 g_Wbl[64 * DIN];       // bf16-lo residual, [n][k]
static __device__ float g_bc[64];                      // combined bias

// ---------------- helpers ----------------
__device__ __forceinline__ float ex2f(float x) {
    float r; asm("ex2.approx.ftz.f32 %0, %1;" : "=f"(r) : "f"(x)); return r;
}
__device__ __forceinline__ float sigf(float x) {
    return __fdividef(1.f, 1.f + __expf(-x));
}
__device__ __forceinline__ float tanhf_fast(float x) {
    float e = __expf(2.f * x);
    return 1.f - __fdividef(2.f, e + 1.f);
}
// f32x2 packed math
__device__ __forceinline__ ull fma2(ull a, ull b, ull c) {
    ull d; asm("fma.rn.f32x2 %0, %1, %2, %3;" : "=l"(d) : "l"(a), "l"(b), "l"(c)); return d;
}
__device__ __forceinline__ ull pack2(float x, float y) {
    ull d; asm("mov.b64 %0, {%1, %2};" : "=l"(d) : "f"(x), "f"(y)); return d;
}
__device__ __forceinline__ float2 unpack2(ull v) {
    float2 r; asm("mov.b64 {%0, %1}, %2;" : "=f"(r.x), "=f"(r.y) : "l"(v)); return r;
}
// pack two f32 -> bf16x2 (first arg -> low half)
__device__ __forceinline__ uint32 packbf(float lo, float hi) {
    uint32 r; asm("cvt.rn.bf16x2.f32 %0, %1, %2;" : "=r"(r) : "f"(hi), "f"(lo)); return r;
}
__device__ __forceinline__ float bflo(uint32 p) { return __uint_as_float(p << 16); }
__device__ __forceinline__ float bfhi(uint32 p) { return __uint_as_float(p & 0xffff0000u); }

__device__ __forceinline__ uint32 smem_u32(const void* p) {
    uint32 a;
    asm("{ .reg .u64 t; cvta.to.shared.u64 t, %1; cvt.u32.u64 %0, t; }" : "=r"(a) : "l"(p));
    return a;
}
__device__ __forceinline__ void ldsm_x4(uint32& r0, uint32& r1, uint32& r2, uint32& r3, uint32 addr) {
    asm volatile("ldmatrix.sync.aligned.m8n8.x4.shared.b16 {%0,%1,%2,%3}, [%4];"
                 : "=r"(r0), "=r"(r1), "=r"(r2), "=r"(r3) : "r"(addr));
}

// bf16 mma m16n8k16, row.col, f32 accumulate
__device__ __forceinline__ void mma_bf16(float* d, const uint32* a, const uint32* b) {
    asm volatile(
        "mma.sync.aligned.m16n8k16.row.col.f32.bf16.bf16.f32 "
        "{%0,%1,%2,%3}, {%4,%5,%6,%7}, {%8,%9}, {%0,%1,%2,%3};"
        : "+f"(d[0]), "+f"(d[1]), "+f"(d[2]), "+f"(d[3])
        : "r"(a[0]), "r"(a[1]), "r"(a[2]), "r"(a[3]), "r"(b[0]), "r"(b[1]));
}

// ---------------- K0: build combined weight, bf16 hi/lo, transposed [n][k] ----------------
__global__ __launch_bounds__(256) void k_prep(
    const float* __restrict__ Wih_f, const float* __restrict__ Wih_b,
    const float* __restrict__ bih_f, const float* __restrict__ bhh_f,
    const float* __restrict__ bih_b, const float* __restrict__ bhh_b)
{
    int n = blockIdx.y;
    int k = blockIdx.x * 256 + threadIdx.x;
    float w = (n < 32) ? Wih_f[n * DIN + k] : Wih_b[(n - 32) * DIN + k];
    __nv_bfloat16 hi = __float2bfloat16_rn(w);
    float res = w - __bfloat162float(hi);
    g_Wbh[n * DIN + k] = hi;
    g_Wbl[n * DIN + k] = __float2bfloat16_rn(res);
    if (blockIdx.x == 0 && blockIdx.y == 0 && threadIdx.x < 64) {
        int i = threadIdx.x;
        g_bc[i] = (i < 32) ? (bih_f[i] + bhh_f[i]) : (bih_b[i - 32] + bhh_b[i - 32]);
    }
}

// ---------------- K1: xproj = X (65536x768) @ Wc (768x64) + bc  (bf16 mma + ldmatrix) ----------------
#define XPITCH 40   // bf16 pitch -> 80-byte rows: 16B-aligned, ldmatrix conflict-free
__global__ __launch_bounds__(256, 2) void k_gemm_xproj(const float* __restrict__ X)
{
    __shared__ alignas(16) __nv_bfloat16 Xh[128 * XPITCH];
    __shared__ alignas(16) __nv_bfloat16 Xl[128 * XPITCH];
    __shared__ alignas(16) __nv_bfloat16 Wh[64 * XPITCH];
    __shared__ alignas(16) __nv_bfloat16 Wl[64 * XPITCH];

    const int tid = threadIdx.x;
    const int rowBase = blockIdx.x * 128;
    const int w = tid >> 5;
    const int lane = tid & 31;
    const int g = lane >> 2;
    const int t4 = lane & 3;

    // ldmatrix per-lane addresses (fixed across chunks: smem reused in place)
    const int sel = lane >> 3;
    const int rowA = w * 16 + (sel & 1) * 8 + (lane & 7);
    const int colA = (sel >> 1) * 16;
    const int rowB = (sel >> 1) * 8 + (lane & 7);
    const int colB = (sel & 1) * 16;
    const uint32 aHi = smem_u32(Xh) + rowA * 80 + colA;
    const uint32 aLo = smem_u32(Xl) + rowA * 80 + colA;
    const uint32 bHi = smem_u32(Wh) + rowB * 80 + colB;
    const uint32 bLo = smem_u32(Wl) + rowB * 80 + colB;

    float acc[8][4];
#pragma unroll
    for (int nt = 0; nt < 8; nt++)
#pragma unroll
        for (int q = 0; q < 4; q++) acc[nt][q] = 0.f;

    float4 vx[4];
    ull vwh[2], vwl[2];

#pragma unroll
    for (int i = 0; i < 4; i++) {
        int idx = i * 256 + tid;
        int r = idx >> 3, k4 = (idx & 7) * 4;
        vx[i] = *(const float4*)(X + (size_t)(rowBase + r) * DIN + k4);
    }
#pragma unroll
    for (int i = 0; i < 2; i++) {
        int idx = i * 256 + tid;
        int n = idx >> 3, k8 = (idx & 7) * 4;
        vwh[i] = *(const ull*)(g_Wbh + n * DIN + k8);
        vwl[i] = *(const ull*)(g_Wbl + n * DIN + k8);
    }

    for (int c = 0; c < 24; c++) {
#pragma unroll
        for (int i = 0; i < 4; i++) {
            int idx = i * 256 + tid;
            int r = idx >> 3, k4 = (idx & 7) * 4;
            float4 v = vx[i];
            __nv_bfloat16 hx = __float2bfloat16_rn(v.x);
            __nv_bfloat16 hy = __float2bfloat16_rn(v.y);
            __nv_bfloat16 hz = __float2bfloat16_rn(v.z);
            __nv_bfloat16 hw = __float2bfloat16_rn(v.w);
            *(__nv_bfloat162*)&Xh[r * XPITCH + k4 + 0] = __nv_bfloat162(hx, hy);
            *(__nv_bfloat162*)&Xh[r * XPITCH + k4 + 2] = __nv_bfloat162(hz, hw);
            *(__nv_bfloat162*)&Xl[r * XPITCH + k4 + 0] = __nv_bfloat162(
                __float2bfloat16_rn(v.x - __bfloat162float(hx)),
                __float2bfloat16_rn(v.y - __bfloat162float(hy)));
            *(__nv_bfloat162*)&Xl[r * XPITCH + k4 + 2] = __nv_bfloat162(
                __float2bfloat16_rn(v.z - __bfloat162float(hz)),
                __float2bfloat16_rn(v.w - __bfloat162float(hw)));
        }
#pragma unroll
        for (int i = 0; i < 2; i++) {
            int idx = i * 256 + tid;
            int n = idx >> 3, k8 = (idx & 7) * 4;
            *(ull*)&Wh[n * XPITCH + k8] = vwh[i];
            *(ull*)&Wl[n * XPITCH + k8] = vwl[i];
        }
        __syncthreads();

        if (c < 23) {
            int k0 = (c + 1) * 32;
#pragma unroll
            for (int i = 0; i < 4; i++) {
                int idx = i * 256 + tid;
                int r = idx >> 3, k4 = (idx & 7) * 4;
                vx[i] = *(const float4*)(X + (size_t)(rowBase + r) * DIN + k0 + k4);
            }
#pragma unroll
            for (int i = 0; i < 2; i++) {
                int idx = i * 256 + tid;
                int n = idx >> 3, k8 = (idx & 7) * 4;
                vwh[i] = *(const ull*)(g_Wbh + n * DIN + k0 + k8);
                vwl[i] = *(const ull*)(g_Wbl + n * DIN + k0 + k8);
            }
        }

#pragma unroll
        for (int ks = 0; ks < 2; ks++) {
            uint32 ah[4], al[4];
            ldsm_x4(ah[0], ah[1], ah[2], ah[3], aHi + ks * 32);
            ldsm_x4(al[0], al[1], al[2], al[3], aLo + ks * 32);
#pragma unroll
            for (int p = 0; p < 4; p++) {
                uint32 bh[4], bl[4];
                ldsm_x4(bh[0], bh[1], bh[2], bh[3], bHi + p * 1280 + ks * 32);
                ldsm_x4(bl[0], bl[1], bl[2], bl[3], bLo + p * 1280 + ks * 32);
                mma_bf16(acc[2 * p], ah, bh);
                mma_bf16(acc[2 * p], ah, bl);
                mma_bf16(acc[2 * p], al, bh);
                mma_bf16(acc[2 * p + 1], ah, bh + 2);
                mma_bf16(acc[2 * p + 1], ah, bl + 2);
                mma_bf16(acc[2 * p + 1], al, bh + 2);
            }
        }
        __syncthreads();
    }

    const int r0 = rowBase + w * 16 + g;
#pragma unroll
    for (int nt = 0; nt < 8; nt++) {
        int cbase = nt * 8 + 2 * t4;
        float b0 = g_bc[cbase], b1 = g_bc[cbase + 1];
        *(float2*)(g_xproj + (size_t)r0 * 64 + cbase) = make_float2(acc[nt][0] + b0, acc[nt][1] + b1);
        *(float2*)(g_xproj + (size_t)(r0 + 8) * 64 + cbase) = make_float2(acc[nt][2] + b0, acc[nt][3] + b1);
    }
}

// ---------------- K2: bi-LSTM scan — smem h-broadcast + f32x2 FMA, 2-way trees ----------------
__global__ __launch_bounds__(64) void k_bilstm(
    const float* __restrict__ Whh_f, const float* __restrict__ Whh_b)
{
    __shared__ float hb[2][8 * 12];

    const int tid = threadIdx.x;
    const int j = tid & 7;
    const int g = tid >> 3;
    const int grp = blockIdx.x * 8 + g;
    const int dir = grp >> 9;
    const int b = grp & 511;
    const float* Whh = dir ? Whh_b : Whh_f;

    ull wp[4][4];
#pragma unroll
    for (int gi = 0; gi < 4; gi++) {
        const float* row = Whh + (gi * 8 + j) * 8;
#pragma unroll
        for (int kk = 0; kk < 4; kk++) wp[gi][kk] = pack2(row[2 * kk], row[2 * kk + 1]);
    }

    hb[0][g * 12 + j] = 0.f;
    float c = 0.f, h = 0.f;

    int t0 = dir ? (T_LEN - 1) : 0;
    int t1 = dir ? (T_LEN - 2) : 1;
    const float* xp0 = g_xproj + ((size_t)t0 * BATCH + b) * 64 + dir * 32;
    const float* xp1 = g_xproj + ((size_t)t1 * BATCH + b) * 64 + dir * 32;
    float n0 = xp0[j], n1 = xp0[8 + j], n2 = xp0[16 + j], n3 = xp0[24 + j];
    float m0 = xp1[j], m1 = xp1[8 + j], m2 = xp1[16 + j], m3 = xp1[24 + j];
    __syncthreads();

    for (int s = 0; s < T_LEN; s++) {
        int t = dir ? (T_LEN - 1 - s) : s;
        float q0 = n0, q1 = n1, q2 = n2, q3 = n3;
        n0 = m0; n1 = m1; n2 = m2; n3 = m3;
        if (s < T_LEN - 2) {
            int tn = dir ? (T_LEN - 3 - s) : (s + 2);
            const float* xn = g_xproj + ((size_t)tn * BATCH + b) * 64 + dir * 32;
            m0 = xn[j]; m1 = xn[8 + j]; m2 = xn[16 + j]; m3 = xn[24 + j];
        }
        const int p = s & 1;
        ull hp[4];
        const ull* hr = (const ull*)&hb[p][g * 12];
#pragma unroll
        for (int kk = 0; kk < 4; kk++) hp[kk] = hr[kk];

        // 2-way trees per gate (depth 2 FFMA2)
        ull a0 = fma2(wp[0][0], hp[0], pack2(q0, 0.f));
        ull b0v = fma2(wp[0][2], hp[2], 0ULL);
        a0 = fma2(wp[0][1], hp[1], a0);
        b0v = fma2(wp[0][3], hp[3], b0v);
        ull a1 = fma2(wp[1][0], hp[0], pack2(q1, 0.f));
        ull b1v = fma2(wp[1][2], hp[2], 0ULL);
        a1 = fma2(wp[1][1], hp[1], a1);
        b1v = fma2(wp[1][3], hp[3], b1v);
        ull a2 = fma2(wp[2][0], hp[0], pack2(q2, 0.f));
        ull b2v = fma2(wp[2][2], hp[2], 0ULL);
        a2 = fma2(wp[2][1], hp[1], a2);
        b2v = fma2(wp[2][3], hp[3], b2v);
        ull a3 = fma2(wp[3][0], hp[0], pack2(q3, 0.f));
        ull b3v = fma2(wp[3][2], hp[2], 0ULL);
        a3 = fma2(wp[3][1], hp[1], a3);
        b3v = fma2(wp[3][3], hp[3], b3v);

        float2 f0 = unpack2(a0), e0 = unpack2(b0v);
        float2 f1 = unpack2(a1), e1 = unpack2(b1v);
        float2 f2 = unpack2(a2), e2 = unpack2(b2v);
        float2 f3 = unpack2(a3), e3 = unpack2(b3v);
        float ig = sigf((f0.x + f0.y) + (e0.x + e0.y));
        float fg = sigf((f1.x + f1.y) + (e1.x + e1.y));
        float gg = tanhf_fast((f2.x + f2.y) + (e2.x + e2.y));
        float og = sigf((f3.x + f3.y) + (e3.x + e3.y));
        c = fg * c + ig * gg;
        h = og * tanhf_fast(c);
        g_h[((size_t)t * BATCH + b) * 16 + dir * 8 + j] = h;
        hb[1 - p][g * 12 + j] = h;
        __syncwarp();
    }
}

// ---------------- K3: ptr-LSTM scan, fused input projection ----------------
// x-part of step t+1's gates computed AFTER h(t) store (hidden behind MUFU/sync shadow);
// h-part is a 2-way FFMA2 tree off the double-buffered smem h broadcast.
__global__ __launch_bounds__(64) void k_ptrlstm(
    const float* __restrict__ Wih_p, const float* __restrict__ Whh_p,
    const float* __restrict__ bih_p, const float* __restrict__ bhh_p)
{
    __shared__ float xs[T_LEN * 80];
    __shared__ float hb[2][4 * 20];

    const int tid = threadIdx.x;
    const int j = tid & 15;
    const int g = tid >> 4;
    const int bbase = blockIdx.x * 4;
    const int b = bbase + g;

    for (int i = tid; i < 2048; i += 64) {
        int t = i >> 4, q = i & 15;
        int item = q >> 2, f4 = q & 3;
        float4 v = *(const float4*)(g_h + (size_t)t * 8192 + (bbase + item) * 16 + f4 * 4);
        *(float4*)&xs[t * 80 + item * 20 + f4 * 4] = v;
    }

    ull wx[4][8], wh[4][8];
    float bias[4];
#pragma unroll
    for (int gi = 0; gi < 4; gi++) {
        int row = gi * 16 + j;
        const float* wi = Wih_p + row * 16;
        const float* wr = Whh_p + row * 16;
#pragma unroll
        for (int kk = 0; kk < 8; kk++) wx[gi][kk] = pack2(wi[2 * kk], wi[2 * kk + 1]);
#pragma unroll
        for (int kk = 0; kk < 8; kk++) wh[gi][kk] = pack2(wr[2 * kk], wr[2 * kk + 1]);
        bias[gi] = bih_p[row] + bhh_p[row];
    }

    hb[0][g * 20 + j] = 0.f;
    float c = 0.f;
    __syncthreads();

    // x-part accumulators for step 0
    ull xa[4];
    {
        const ull* xr = (const ull*)&xs[g * 20];
        ull xv[8];
#pragma unroll
        for (int kk = 0; kk < 8; kk++) xv[kk] = xr[kk];
#pragma unroll
        for (int gi = 0; gi < 4; gi++) {
            ull s0 = fma2(wx[gi][0], xv[0], pack2(bias[gi], 0.f));
            ull s1 = fma2(wx[gi][1], xv[1], 0ULL);
#pragma unroll
            for (int kk = 2; kk < 8; kk += 2) {
                s0 = fma2(wx[gi][kk], xv[kk], s0);
                s1 = fma2(wx[gi][kk + 1], xv[kk + 1], s1);
            }
            xa[gi] = fma2(pack2(1.f, 1.f), s1, s0);   // combine trees
        }
    }

    for (int t = 0; t < T_LEN; t++) {
        const int p = t & 1;
        const ull* hr = (const ull*)&hb[p][g * 20];
        ull hv[8];
#pragma unroll
        for (int kk = 0; kk < 8; kk++) hv[kk] = hr[kk];

        // h-part: 2-way tree per gate, seeded with precomputed x-part
        ull s0a = fma2(wh[0][0], hv[0], xa[0]);
        ull s0b = fma2(wh[0][1], hv[1], 0ULL);
        ull s1a = fma2(wh[1][0], hv[0], xa[1]);
        ull s1b = fma2(wh[1][1], hv[1], 0ULL);
        ull s2a = fma2(wh[2][0], hv[0], xa[2]);
        ull s2b = fma2(wh[2][1], hv[1], 0ULL);
        ull s3a = fma2(wh[3][0], hv[0], xa[3]);
        ull s3b = fma2(wh[3][1], hv[1], 0ULL);
#pragma unroll
        for (int kk = 2; kk < 8; kk += 2) {
            s0a = fma2(wh[0][kk], hv[kk], s0a);
            s0b = fma2(wh[0][kk + 1], hv[kk + 1], s0b);
            s1a = fma2(wh[1][kk], hv[kk], s1a);
            s1b = fma2(wh[1][kk + 1], hv[kk + 1], s1b);
            s2a = fma2(wh[2][kk], hv[kk], s2a);
            s2b = fma2(wh[2][kk + 1], hv[kk + 1], s2b);
            s3a = fma2(wh[3][kk], hv[kk], s3a);
            s3b = fma2(wh[3][kk + 1], hv[kk + 1], s3b);
        }
        float2 f0 = unpack2(s0a), e0 = unpack2(s0b);
        float2 f1 = unpack2(s1a), e1 = unpack2(s1b);
        float2 f2 = unpack2(s2a), e2 = unpack2(s2b);
        float2 f3 = unpack2(s3a), e3 = unpack2(s3b);
        float ig = sigf((f0.x + f0.y) + (e0.x + e0.y));
        float fg = sigf((f1.x + f1.y) + (e1.x + e1.y));
        float gg = tanhf_fast((f2.x + f2.y) + (e2.x + e2.y));
        float og = sigf((f3.x + f3.y) + (e3.x + e3.y));
        c = fg * c + ig * gg;
        float h = og * tanhf_fast(c);
        g_z[((size_t)t * BATCH + b) * 16 + j] = h;
        hb[1 - p][g * 20 + j] = h;

        // overlap: x-part for step t+1 (independent of h(t+1) broadcast)
        if (t < T_LEN - 1) {
            const ull* xr = (const ull*)&xs[(t + 1) * 80 + g * 20];
            ull xv[8];
#pragma unroll
            for (int kk = 0; kk < 8; kk++) xv[kk] = xr[kk];
#pragma unroll
            for (int gi = 0; gi < 4; gi++) {
                ull u0 = fma2(wx[gi][0], xv[0], pack2(bias[gi], 0.f));
                ull u1 = fma2(wx[gi][1], xv[1], 0ULL);
#pragma unroll
                for (int kk = 2; kk < 8; kk += 2) {
                    u0 = fma2(wx[gi][kk], xv[kk], u0);
                    u1 = fma2(wx[gi][kk + 1], xv[kk + 1], u1);
                }
                xa[gi] = fma2(pack2(1.f, 1.f), u1, u0);
            }
        }
        __syncwarp();
    }
}

// ---------------- K4: tensor-core attention + output head, one CTA per t ----------------
#define HP 20
#define HTP 516
#define OFF_HHI   0
#define OFF_HLO   20480
#define OFF_ZHI   40960
#define OFF_ZLO   61440
#define OFF_HT    81920
#define OFF_CP    114944
#define OFF_INV   117248
#define OFF_CTX   117376
#define OFF_WH    152192
#define OFF_WE    153216
#define OFF_WV    154240
#define ATT_SMEM  154304

__global__ __launch_bounds__(512, 1) void k_attn(
    const float* __restrict__ W_h, const float* __restrict__ W_e,
    const float* __restrict__ W_v, float* __restrict__ out)
{
    extern __shared__ char smc[];
    __nv_bfloat16* hhi = (__nv_bfloat16*)(smc + OFF_HHI);
    __nv_bfloat16* hlo = (__nv_bfloat16*)(smc + OFF_HLO);
    __nv_bfloat16* zhi = (__nv_bfloat16*)(smc + OFF_ZHI);
    __nv_bfloat16* zlo = (__nv_bfloat16*)(smc + OFF_ZLO);
    float* hT   = (float*)(smc + OFF_HT);
    float* cp   = (float*)(smc + OFF_CP);
    float* invs = (float*)(smc + OFF_INV);
    float* ctx  = (float*)(smc + OFF_CTX);
    float* sWh  = (float*)(smc + OFF_WH);
    float* sWe  = (float*)(smc + OFF_WE);
    float* sWv  = (float*)(smc + OFF_WV);

    const int t = blockIdx.x, tid = threadIdx.x;
    const int w = tid >> 5, lane = tid & 31;
    const int qr = lane >> 2, qc = lane & 3;
    const float LOG2E = 1.4426950408889634f;

    const float4* hg = (const float4*)(g_h + (size_t)t * 8192);
    const float4* zg = (const float4*)(g_z + (size_t)t * 8192);
#pragma unroll
    for (int it = 0; it < 4; it++) {
        int i = it * 512 + tid;
        int r = i >> 2, d4 = (i & 3) * 4;
        float4 v = hg[i];
        uint32 h01 = packbf(v.x, v.y), h23 = packbf(v.z, v.w);
        *(uint32*)&hhi[r * HP + d4]     = h01;
        *(uint32*)&hhi[r * HP + d4 + 2] = h23;
        *(uint32*)&hlo[r * HP + d4]     = packbf(v.x - bflo(h01), v.y - bfhi(h01));
        *(uint32*)&hlo[r * HP + d4 + 2] = packbf(v.z - bflo(h23), v.w - bfhi(h23));
        hT[(d4 + 0) * HTP + r] = v.x;
        hT[(d4 + 1) * HTP + r] = v.y;
        hT[(d4 + 2) * HTP + r] = v.z;
        hT[(d4 + 3) * HTP + r] = v.w;
        float4 u = zg[i];
        u.x *= LOG2E; u.y *= LOG2E; u.z *= LOG2E; u.w *= LOG2E;
        uint32 z01 = packbf(u.x, u.y), z23 = packbf(u.z, u.w);
        *(uint32*)&zhi[r * HP + d4]     = z01;
        *(uint32*)&zhi[r * HP + d4 + 2] = z23;
        *(uint32*)&zlo[r * HP + d4]     = packbf(u.x - bflo(z01), u.y - bfhi(z01));
        *(uint32*)&zlo[r * HP + d4 + 2] = packbf(u.z - bflo(z23), u.w - bfhi(z23));
    }
    if (tid < 256) { sWh[tid] = W_h[tid]; sWe[tid] = W_e[tid]; }
    if (tid < 16)  sWv[tid] = W_v[tid];
    __syncthreads();

    uint32 Ahh[2][4], Ahl[2][4];
#pragma unroll
    for (int mt = 0; mt < 2; mt++) {
        int row = 32 * w + 16 * mt + qr;
        int base = row * HP + 2 * qc;
        Ahh[mt][0] = *(const uint32*)&hhi[base];
        Ahh[mt][1] = *(const uint32*)&hhi[base + 8 * HP];
        Ahh[mt][2] = *(const uint32*)&hhi[base + 8];
        Ahh[mt][3] = *(const uint32*)&hhi[base + 8 * HP + 8];
        Ahl[mt][0] = *(const uint32*)&hlo[base];
        Ahl[mt][1] = *(const uint32*)&hlo[base + 8 * HP];
        Ahl[mt][2] = *(const uint32*)&hlo[base + 8];
        Ahl[mt][3] = *(const uint32*)&hlo[base + 8 * HP + 8];
    }

    float ctxacc[2][2][4];
#pragma unroll
    for (int mt = 0; mt < 2; mt++)
#pragma unroll
        for (int nt = 0; nt < 2; nt++)
#pragma unroll
            for (int q = 0; q < 4; q++) ctxacc[mt][nt][q] = 0.f;

    for (int tile = 0; tile < 16; tile++) {
        const int c0 = tile * 32;
        uint32 Aeh[2][2][4], Ael[2][2][4];

#pragma unroll
        for (int nt = 0; nt < 4; nt++) {
            int crow = c0 + 8 * nt + qr;
            int zb = crow * HP + 2 * qc;
            uint32 bzh[2], bzl[2];
            bzh[0] = *(const uint32*)&zhi[zb];
            bzh[1] = *(const uint32*)&zhi[zb + 8];
            bzl[0] = *(const uint32*)&zlo[zb];
            bzl[1] = *(const uint32*)&zlo[zb + 8];
            float P0 = 0.f, P1 = 0.f;
            const int ks = nt >> 1, hf = nt & 1;
#pragma unroll
            for (int mt = 0; mt < 2; mt++) {
                float S[4] = {0.f, 0.f, 0.f, 0.f};
                mma_bf16(S, Ahh[mt], bzh);
                mma_bf16(S, Ahh[mt], bzl);
                mma_bf16(S, Ahl[mt], bzh);
                float e0 = ex2f(S[0]), e1 = ex2f(S[1]), e2 = ex2f(S[2]), e3 = ex2f(S[3]);
                P0 += e0 + e2; P1 += e1 + e3;
                uint32 p01 = packbf(e0, e1), p23 = packbf(e2, e3);
                Aeh[mt][ks][2 * hf]     = p01;
                Aeh[mt][ks][2 * hf + 1] = p23;
                Ael[mt][ks][2 * hf]     = packbf(e0 - bflo(p01), e1 - bfhi(p01));
                Ael[mt][ks][2 * hf + 1] = packbf(e2 - bflo(p23), e3 - bfhi(p23));
            }
            P0 += __shfl_xor_sync(0xffffffffu, P0, 4);
            P0 += __shfl_xor_sync(0xffffffffu, P0, 8);
            P0 += __shfl_xor_sync(0xffffffffu, P0, 16);
            P1 += __shfl_xor_sync(0xffffffffu, P1, 4);
            P1 += __shfl_xor_sync(0xffffffffu, P1, 8);
            P1 += __shfl_xor_sync(0xffffffffu, P1, 16);
            if (qr == 0) {
                cp[w * 36 + 8 * nt + 2 * qc]     = P0;
                cp[w * 36 + 8 * nt + 2 * qc + 1] = P1;
            }
        }
        __syncthreads();
        if (tid < 32) {
            float s = 0.f;
#pragma unroll
            for (int ww = 0; ww < 16; ww++) s += cp[ww * 36 + tid];
            invs[tid] = __fdividef(1.f, s);
        }
        __syncthreads();

#pragma unroll
        for (int ks = 0; ks < 2; ks++) {
#pragma unroll
            for (int nt2 = 0; nt2 < 2; nt2++) {
                int d = 8 * nt2 + qr;
                int cc = 16 * ks + 2 * qc;
                float i0 = invs[cc], i1 = invs[cc + 1], i8 = invs[cc + 8], i9 = invs[cc + 9];
                const float* hr = hT + d * HTP + c0 + cc;
                float v0 = hr[0] * i0, v1 = hr[1] * i1, v8 = hr[8] * i8, v9 = hr[9] * i9;
                uint32 bh[2], bl[2];
                bh[0] = packbf(v0, v1);
                bh[1] = packbf(v8, v9);
                bl[0] = packbf(v0 - bflo(bh[0]), v1 - bfhi(bh[0]));
                bl[1] = packbf(v8 - bflo(bh[1]), v9 - bfhi(bh[1]));
#pragma unroll
                for (int mt = 0; mt < 2; mt++) {
                    mma_bf16(ctxacc[mt][nt2], Aeh[mt][ks], bh);
                    mma_bf16(ctxacc[mt][nt2], Ael[mt][ks], bh);
                    mma_bf16(ctxacc[mt][nt2], Aeh[mt][ks], bl);
                }
            }
        }
    }

#pragma unroll
    for (int mt = 0; mt < 2; mt++)
#pragma unroll
        for (int nt2 = 0; nt2 < 2; nt2++) {
            int row = 32 * w + 16 * mt + qr;
            int col = 8 * nt2 + 2 * qc;
            ctx[row * 17 + col]           = ctxacc[mt][nt2][0];
            ctx[row * 17 + col + 1]       = ctxacc[mt][nt2][1];
            ctx[(row + 8) * 17 + col]     = ctxacc[mt][nt2][2];
            ctx[(row + 8) * 17 + col + 1] = ctxacc[mt][nt2][3];
        }
    __syncthreads();

    {
        int b = tid;
        float hb2[16], cx[16];
        const float4* hp4 = (const float4*)(g_h + (size_t)t * 8192 + b * 16);
#pragma unroll
        for (int q = 0; q < 4; q++) {
            float4 v = hp4[q];
            hb2[4 * q + 0] = v.x; hb2[4 * q + 1] = v.y; hb2[4 * q + 2] = v.z; hb2[4 * q + 3] = v.w;
        }
#pragma unroll
        for (int k = 0; k < 16; k++) cx[k] = ctx[b * 17 + k];
        float pv = 0.f;
#pragma unroll
        for (int r = 0; r < 16; r++) {
            float a = 0.f;
#pragma unroll
            for (int k = 0; k < 16; k++)
                a += sWh[r * 16 + k] * hb2[k] + sWe[r * 16 + k] * cx[k];
            pv += sWv[r] * tanhf_fast(a);
        }
        out[(size_t)t * BATCH + b] = sigf(pv);
    }
}

// ---------------- launch ----------------
extern "C" void kernel_launch(void* const* d_in, const int* in_sizes, int n_in,
                              void* d_out, int out_size)
{
    const float* X     = (const float*)d_in[0];
    const float* Wih_f = (const float*)d_in[1];
    const float* Whh_f = (const float*)d_in[2];
    const float* bih_f = (const float*)d_in[3];
    const float* bhh_f = (const float*)d_in[4];
    const float* Wih_b = (const float*)d_in[5];
    const float* Whh_b = (const float*)d_in[6];
    const float* bih_b = (const float*)d_in[7];
    const float* bhh_b = (const float*)d_in[8];
    const float* Wih_p = (const float*)d_in[9];
    const float* Whh_p = (const float*)d_in[10];
    const float* bih_p = (const float*)d_in[11];
    const float* bhh_p = (const float*)d_in[12];
    const float* W_h   = (const float*)d_in[13];
    const float* W_e   = (const float*)d_in[14];
    const float* W_v   = (const float*)d_in[15];
    float* out = (float*)d_out;

    cudaFuncSetAttribute((const void*)k_attn, cudaFuncAttributeMaxDynamicSharedMemorySize, 160 * 1024);

    k_prep<<<dim3(3, 64), 256>>>(Wih_f, Wih_b, bih_f, bhh_f, bih_b, bhh_b);
    k_gemm_xproj<<<(T_LEN * BATCH) / 128, 256>>>(X);
    k_bilstm<<<128, 64>>>(Whh_f, Whh_b);
    k_ptrlstm<<<128, 64>>>(Wih_p, Whh_p, bih_p, bhh_p);
    k_attn<<<T_LEN, 512, ATT_SMEM>>>(W_h, W_e, W_v, out);
}